// round 16
// baseline (speedup 1.0000x reference)
#include <cuda_runtime.h>
#include <cuda_fp16.h>
#include <cuda_bf16.h>
#include <mma.h>
#include <cstdint>

using namespace nvcuda;

#define N_NODES 100000
#define N_EDGES_MAX 2000000                        // real 1.6M + pad (<=300K)
#define F 128
#define BN_EPS 1e-5f
#define CHUNK 1024
#define NCHUNKS ((N_NODES + CHUNK - 1) / CHUNK)   // 98
#define M_TILE 256
#define N_PAD 100096                               // 391 * 256
#define GEMM_BLOCKS (N_PAD / M_TILE)               // 391
#define GEMM_GRID 148                              // persistent: one CTA per SM
#define GEMM_WAVES ((GEMM_BLOCKS + GEMM_GRID - 1) / GEMM_GRID)  // 3
#define A_STRIDE 136                               // padded smem lda (bf16)
#define B_STRIDE 136
#define SPMM_GRID 888                              // 148 SMs * 6 resident blocks
#define SPMM_WARPS (SPMM_GRID * 8)                 // 7104
#define ROWS_PER_WARP ((N_NODES + SPMM_WARPS - 1) / SPMM_WARPS)  // 15

// Dynamic smem layout for GEMM (bytes)
#define SM_AHI 0
#define SM_ALO (M_TILE * A_STRIDE * 2)             // 69632
#define SM_BHI (2 * M_TILE * A_STRIDE * 2)         // 139264
#define SM_BLO (SM_BHI + F * B_STRIDE * 2)         // +34816
#define GEMM_SMEM (SM_BLO + F * B_STRIDE * 2)      // 208896

// ---------------------------------------------------------------------------
// Scratch (__device__ globals; allocation-free rule).
// g_ecw is zero-initialized at module load. Pad slots are NEVER written and
// the CSR layout is replay-invariant, so pad entries stay {col=0, w=0.0f}
// forever (validated R13/R14).
// ---------------------------------------------------------------------------
__device__ __half g_a[(size_t)N_PAD * F];      // t1 = x@W1, later h2 (fp16)
__device__ float  g_b[(size_t)N_PAD * F];      // h1 (fp32; pad rows stay 0)
__device__ float  g_stats[2 * F];              // [sum, sumsq] per feature
__device__ int    g_count[N_NODES];            // REAL counts; zeroed at launch end
__device__ int    g_row_start[N_NODES + 1];    // chunk-local excl prefix of PADDED counts
__device__ int    g_cursor[N_NODES];
__device__ int    g_chunksum[NCHUNKS];
__device__ int    g_chunkoff[NCHUNKS];
__device__ int    g_ticket;                    // reset by scan1 finisher
__device__ int2   g_ecw[N_EDGES_MAX];          // row-grouped {col, weight-bits}, rows padded to 4
__device__ __nv_bfloat16 g_w1hi[F * F];
__device__ __nv_bfloat16 g_w1lo[F * F];
__device__ __nv_bfloat16 g_w2hi[F * F];
__device__ __nv_bfloat16 g_w2lo[F * F];

// ---------------------------------------------------------------------------
// Prep: zero stats + split W1/W2 into bf16 hi/lo + edge histogram.
// ---------------------------------------------------------------------------
__global__ void prep_kernel(const float* __restrict__ W1, const float* __restrict__ W2,
                            const int* __restrict__ erow, int E) {
    int idx = blockIdx.x * blockDim.x + threadIdx.x;
    int stride = gridDim.x * blockDim.x;
    if (idx < 2 * F) g_stats[idx] = 0.0f;

    for (int i = idx; i < 2 * F * F; i += stride) {
        int m = i >> 14;
        int e = i & (F * F - 1);
        float w = m ? W2[e] : W1[e];
        __nv_bfloat16 hi = __float2bfloat16_rn(w);
        __nv_bfloat16 lo = __float2bfloat16_rn(w - __bfloat162float(hi));
        if (m) { g_w2hi[e] = hi; g_w2lo[e] = lo; }
        else   { g_w1hi[e] = hi; g_w1lo[e] = lo; }
    }

    for (int e = idx; e < E; e += stride)
        atomicAdd(&g_count[erow[e]], 1);
}

// ---------------------------------------------------------------------------
// Per-chunk scan of PADDED counts + last-block finalize (and ticket reset).
// ---------------------------------------------------------------------------
__global__ void scan1_kernel() {
    __shared__ int sm[CHUNK];
    __shared__ int is_last;
    int tid = threadIdx.x;
    int i = blockIdx.x * CHUNK + tid;
    int val = (i < N_NODES) ? ((g_count[i] + 3) & ~3) : 0;   // padded
    sm[tid] = val;
    __syncthreads();
    for (int off = 1; off < CHUNK; off <<= 1) {
        int t = (tid >= off) ? sm[tid - off] : 0;
        __syncthreads();
        sm[tid] += t;
        __syncthreads();
    }
    int excl = sm[tid] - val;
    if (i < N_NODES + 1) g_row_start[i] = excl;
    if (i < N_NODES) g_cursor[i] = excl;
    if (tid == CHUNK - 1) g_chunksum[blockIdx.x] = sm[tid];

    if (tid == 0) {
        __threadfence();
        is_last = (atomicAdd(&g_ticket, 1) == NCHUNKS - 1);
    }
    __syncthreads();
    if (is_last) {
        __shared__ int cs[128];
        if (tid < 128) {
            int v = (tid < NCHUNKS) ? g_chunksum[tid] : 0;
            cs[tid] = v;
            __syncwarp();
        }
        __syncthreads();
        if (tid < 128) {
            for (int off = 1; off < 128; off <<= 1) {
                int t = (tid >= off) ? cs[tid - off] : 0;
                __syncthreads();
                cs[tid] += t;
                __syncthreads();
            }
            if (tid < NCHUNKS) g_chunkoff[tid] = cs[tid] - ((tid < NCHUNKS) ? g_chunksum[tid] : 0);
            if (tid == 0) g_ticket = 0;
        } else {
            for (int off = 1; off < 128; off <<= 1) { __syncthreads(); __syncthreads(); }
        }
    }
}

// ---------------------------------------------------------------------------
// Persistent WMMA bf16 GEMM, 3-term split: outH(fp16) = transform(X fp32) @ W.
// Grid = 148; B copied to smem once; DIRECT fp16 fragment epilogue (float
// acc -> half acc elementwise, store_matrix_sync to global; no smem staging).
// DO_SCATTER pre-phase: scatter real edges (pad slots stay zero from load).
// ---------------------------------------------------------------------------
template <bool FUSE_BN, bool DO_SCATTER>
__global__ void __launch_bounds__(512, 1) gemm_wmma_kernel(
    const float* __restrict__ X,
    const __nv_bfloat16* __restrict__ Whi, const __nv_bfloat16* __restrict__ Wlo,
    __half* __restrict__ outH, int nrows,
    const float* __restrict__ gamma, const float* __restrict__ beta,
    const int* __restrict__ erow, const int* __restrict__ ecol,
    const float* __restrict__ ew, int E) {
    extern __shared__ char smem[];
    __nv_bfloat16* a_hi = (__nv_bfloat16*)(smem + SM_AHI);
    __nv_bfloat16* a_lo = (__nv_bfloat16*)(smem + SM_ALO);
    __nv_bfloat16* b_hi = (__nv_bfloat16*)(smem + SM_BHI);
    __nv_bfloat16* b_lo = (__nv_bfloat16*)(smem + SM_BLO);
    __shared__ float scale_s[F];
    __shared__ float shift_s[F];

    const int tid = threadIdx.x;
    const int wid = tid >> 5;
    const int wm = wid & 7;
    const int wn = wid >> 3;
    const int mrow0 = wm * 32;
    const int ncol0 = wn * 64;

    if (DO_SCATTER) {
        int per = (E + gridDim.x - 1) / (int)gridDim.x;
        int e0 = blockIdx.x * per;
        int e1 = min(e0 + per, E);
        for (int e = e0 + tid; e < e1; e += 512) {
            int r = erow[e];
            int pos = atomicAdd(&g_cursor[r], 1) + g_chunkoff[r >> 10];
            g_ecw[pos] = make_int2(ecol[e], __float_as_int(ew[e]));
        }
    }

    if (FUSE_BN && tid < F) {
        const float inv = 1.0f / (float)N_NODES;
        float mean = g_stats[tid] * inv;
        float var = g_stats[F + tid] * inv - mean * mean;
        float sc = gamma[tid] * rsqrtf(var + BN_EPS);
        scale_s[tid] = sc;
        shift_s[tid] = beta[tid] - mean * sc;
    }

    // Copy B hi/lo into padded smem ONCE (amortized over all tiles)
    {
        const uint2* Bh = (const uint2*)Whi;
        const uint2* Bl = (const uint2*)Wlo;
        for (int i = tid; i < F * 32; i += 512) {
            int r = i >> 5;
            int c = i & 31;
            ((uint2*)&b_hi[r * B_STRIDE])[c] = Bh[i];
            ((uint2*)&b_lo[r * B_STRIDE])[c] = Bl[i];
        }
    }

    const float4* X4 = (const float4*)X;

    for (int wave = 0; wave < GEMM_WAVES; wave++) {
        const int tile = (int)blockIdx.x + wave * GEMM_GRID;
        const bool active = (tile < GEMM_BLOCKS);
        const int row0 = tile * M_TILE;

        // Orders: prev wave's MMA reads of a_hi/a_lo before overwrite;
        // B copy & scale_s before first use.
        __syncthreads();

        if (active) {
            const bool full = (row0 + M_TILE <= nrows);
            for (int i = tid; i < M_TILE * 32; i += 512) {
                int r = i >> 5;
                int c4 = i & 31;
                int gr = row0 + r;
                float4 v = make_float4(0.f, 0.f, 0.f, 0.f);
                if (full || gr < nrows) v = X4[(size_t)gr * 32 + c4];
                if (FUSE_BN) {
                    int f = c4 * 4;
                    v.x = fmaxf(fmaf(v.x, scale_s[f + 0], shift_s[f + 0]), 0.f);
                    v.y = fmaxf(fmaf(v.y, scale_s[f + 1], shift_s[f + 1]), 0.f);
                    v.z = fmaxf(fmaf(v.z, scale_s[f + 2], shift_s[f + 2]), 0.f);
                    v.w = fmaxf(fmaf(v.w, scale_s[f + 3], shift_s[f + 3]), 0.f);
                }
                __nv_bfloat16 hx = __float2bfloat16_rn(v.x), hy = __float2bfloat16_rn(v.y);
                __nv_bfloat16 hz = __float2bfloat16_rn(v.z), hw = __float2bfloat16_rn(v.w);
                __nv_bfloat16 lx = __float2bfloat16_rn(v.x - __bfloat162float(hx));
                __nv_bfloat16 ly = __float2bfloat16_rn(v.y - __bfloat162float(hy));
                __nv_bfloat16 lz = __float2bfloat16_rn(v.z - __bfloat162float(hz));
                __nv_bfloat16 lw = __float2bfloat16_rn(v.w - __bfloat162float(hw));
                int base = r * A_STRIDE + c4 * 4;
                uint2 hp, lp;
                hp.x = (uint32_t)__bfloat16_as_ushort(hx) | ((uint32_t)__bfloat16_as_ushort(hy) << 16);
                hp.y = (uint32_t)__bfloat16_as_ushort(hz) | ((uint32_t)__bfloat16_as_ushort(hw) << 16);
                lp.x = (uint32_t)__bfloat16_as_ushort(lx) | ((uint32_t)__bfloat16_as_ushort(ly) << 16);
                lp.y = (uint32_t)__bfloat16_as_ushort(lz) | ((uint32_t)__bfloat16_as_ushort(lw) << 16);
                *(uint2*)&a_hi[base] = hp;
                *(uint2*)&a_lo[base] = lp;
            }
        }
        __syncthreads();

        if (active) {
            wmma::fragment<wmma::accumulator, 16, 16, 16, float> acc[2][4];
#pragma unroll
            for (int mt = 0; mt < 2; mt++)
#pragma unroll
                for (int nt = 0; nt < 4; nt++)
                    wmma::fill_fragment(acc[mt][nt], 0.0f);

#pragma unroll
            for (int k0 = 0; k0 < F; k0 += 16) {
                wmma::fragment<wmma::matrix_a, 16, 16, 16, __nv_bfloat16, wmma::row_major> ah[2], al[2];
#pragma unroll
                for (int mt = 0; mt < 2; mt++) {
                    wmma::load_matrix_sync(ah[mt], &a_hi[(mrow0 + mt * 16) * A_STRIDE + k0], A_STRIDE);
                    wmma::load_matrix_sync(al[mt], &a_lo[(mrow0 + mt * 16) * A_STRIDE + k0], A_STRIDE);
                }
#pragma unroll
                for (int nt = 0; nt < 4; nt++) {
                    wmma::fragment<wmma::matrix_b, 16, 16, 16, __nv_bfloat16, wmma::row_major> bh, bl;
                    wmma::load_matrix_sync(bh, &b_hi[k0 * B_STRIDE + ncol0 + nt * 16], B_STRIDE);
                    wmma::load_matrix_sync(bl, &b_lo[k0 * B_STRIDE + ncol0 + nt * 16], B_STRIDE);
#pragma unroll
                    for (int mt = 0; mt < 2; mt++) {
                        wmma::mma_sync(acc[mt][nt], ah[mt], bh, acc[mt][nt]);
                        wmma::mma_sync(acc[mt][nt], al[mt], bh, acc[mt][nt]);
                        wmma::mma_sync(acc[mt][nt], ah[mt], bl, acc[mt][nt]);
                    }
                }
            }

            // Direct fp16 epilogue: float acc -> half acc fragment -> global.
            // (m16n16k16 float/half accumulator thread-element mappings match;
            // standard FasterTransformer conversion pattern.)
#pragma unroll
            for (int mt = 0; mt < 2; mt++) {
                int gr = row0 + mrow0 + mt * 16;
#pragma unroll
                for (int nt = 0; nt < 4; nt++) {
                    wmma::fragment<wmma::accumulator, 16, 16, 16, __half> hacc;
#pragma unroll
                    for (int i = 0; i < hacc.num_elements; i++)
                        hacc.x[i] = __float2half_rn(acc[mt][nt].x[i]);
                    wmma::store_matrix_sync(&outH[(size_t)gr * F + ncol0 + nt * 16],
                                            hacc, F, wmma::mem_row_major);
                }
            }
        }
    }
}

// ---------------------------------------------------------------------------
// CSR SpMM v6: CONTIGUOUS row range per warp (register-carried row bounds:
// one sequential L1-hot row_start load per row instead of two scattered);
// padded rows -> branch-free 4-wide loop; 4 fp16 gathers in flight.
// ---------------------------------------------------------------------------
template <bool STATS, bool ZERO_COUNT>
__global__ void __launch_bounds__(256, 6) spmm_csr_kernel(
    const __half* __restrict__ src, float* __restrict__ dst,
    const float* __restrict__ bias) {
    const int lane = threadIdx.x & 31;
    const int wid = threadIdx.x >> 5;
    const int gwarp = (blockIdx.x * blockDim.x + threadIdx.x) >> 5;

    const uint2* lane_src = (const uint2*)src + lane;   // per-lane base (4 halves)
    float4* dst4 = (float4*)dst;
    const float4 bias4 = ((const float4*)bias)[lane];

    float4 ls = make_float4(0.f, 0.f, 0.f, 0.f);
    float4 lq = make_float4(0.f, 0.f, 0.f, 0.f);

    const int r0 = gwarp * ROWS_PER_WARP;
    const int r1 = min(r0 + ROWS_PER_WARP, N_NODES);

    if (r0 < N_NODES) {
        int s = g_row_start[r0] + g_chunkoff[r0 >> 10];   // absolute; carried
        for (int r = r0; r < r1; r++) {
            const int e = g_row_start[r + 1] + g_chunkoff[(r + 1) >> 10];
            float4 acc = bias4;
            for (int j = s; j < e; j += 4) {             // e-s is a multiple of 4
                const int4 ma = *(const int4*)(g_ecw + j);       // edges j, j+1
                const int4 mb = *(const int4*)(g_ecw + j + 2);   // edges j+2, j+3
                uint2 p0 = lane_src[(size_t)ma.x * 32];          // 4 gathers in flight
                uint2 p1 = lane_src[(size_t)ma.z * 32];
                uint2 p2 = lane_src[(size_t)mb.x * 32];
                uint2 p3 = lane_src[(size_t)mb.z * 32];
                float w0 = __int_as_float(ma.y);
                float w1 = __int_as_float(ma.w);
                float w2 = __int_as_float(mb.y);
                float w3 = __int_as_float(mb.w);
                float2 a0 = __half22float2(*(const __half2*)&p0.x);
                float2 b0 = __half22float2(*(const __half2*)&p0.y);
                acc.x = fmaf(a0.x, w0, acc.x); acc.y = fmaf(a0.y, w0, acc.y);
                acc.z = fmaf(b0.x, w0, acc.z); acc.w = fmaf(b0.y, w0, acc.w);
                float2 a1 = __half22float2(*(const __half2*)&p1.x);
                float2 b1 = __half22float2(*(const __half2*)&p1.y);
                acc.x = fmaf(a1.x, w1, acc.x); acc.y = fmaf(a1.y, w1, acc.y);
                acc.z = fmaf(b1.x, w1, acc.z); acc.w = fmaf(b1.y, w1, acc.w);
                float2 a2 = __half22float2(*(const __half2*)&p2.x);
                float2 b2 = __half22float2(*(const __half2*)&p2.y);
                acc.x = fmaf(a2.x, w2, acc.x); acc.y = fmaf(a2.y, w2, acc.y);
                acc.z = fmaf(b2.x, w2, acc.z); acc.w = fmaf(b2.y, w2, acc.w);
                float2 a3 = __half22float2(*(const __half2*)&p3.x);
                float2 b3 = __half22float2(*(const __half2*)&p3.y);
                acc.x = fmaf(a3.x, w3, acc.x); acc.y = fmaf(a3.y, w3, acc.y);
                acc.z = fmaf(b3.x, w3, acc.z); acc.w = fmaf(b3.y, w3, acc.w);
            }
            dst4[(size_t)r * 32 + lane] = acc;
            if (STATS) {
                ls.x += acc.x; ls.y += acc.y; ls.z += acc.z; ls.w += acc.w;
                lq.x = fmaf(acc.x, acc.x, lq.x);
                lq.y = fmaf(acc.y, acc.y, lq.y);
                lq.z = fmaf(acc.z, acc.z, lq.z);
                lq.w = fmaf(acc.w, acc.w, lq.w);
            }
            s = e;                                        // carry end -> next start
        }
    }

    if (STATS) {
        __shared__ float ssum[8 * F];
        __shared__ float ssq[8 * F];
        *(float4*)&ssum[wid * F + lane * 4] = ls;
        *(float4*)&ssq[wid * F + lane * 4] = lq;
        __syncthreads();
        int tid = threadIdx.x;
        if (tid < F) {
            float s2 = 0.f;
#pragma unroll
            for (int w = 0; w < 8; w++) s2 += ssum[w * F + tid];
            atomicAdd(&g_stats[tid], s2);
        } else {
            int f = tid - F;
            float q = 0.f;
#pragma unroll
            for (int w = 0; w < 8; w++) q += ssq[w * F + f];
            atomicAdd(&g_stats[F + f], q);
        }
    }

    if (ZERO_COUNT) {
        for (int i = blockIdx.x * blockDim.x + threadIdx.x; i < N_NODES;
             i += gridDim.x * blockDim.x)
            g_count[i] = 0;
    }
}

// ---------------------------------------------------------------------------
// Launch
// ---------------------------------------------------------------------------
extern "C" void kernel_launch(void* const* d_in, const int* in_sizes, int n_in,
                              void* d_out, int out_size) {
    const float* x     = (const float*)d_in[0];
    const int*   erow  = (const int*)d_in[1];
    const int*   ecol  = (const int*)d_in[2];
    const float* ew    = (const float*)d_in[3];
    const float* W1    = (const float*)d_in[4];
    const float* b1    = (const float*)d_in[5];
    const float* W2    = (const float*)d_in[6];
    const float* b2    = (const float*)d_in[7];
    const float* gamma = (const float*)d_in[8];
    const float* beta  = (const float*)d_in[9];
    float* out = (float*)d_out;
    const int E = in_sizes[1];

    __half* ga;
    float* gb;
    cudaGetSymbolAddress((void**)&ga, g_a);
    cudaGetSymbolAddress((void**)&gb, g_b);
    __nv_bfloat16 *w1h, *w1l, *w2h, *w2l;
    cudaGetSymbolAddress((void**)&w1h, g_w1hi);
    cudaGetSymbolAddress((void**)&w1l, g_w1lo);
    cudaGetSymbolAddress((void**)&w2h, g_w2hi);
    cudaGetSymbolAddress((void**)&w2l, g_w2lo);

    cudaFuncSetAttribute((const void*)gemm_wmma_kernel<false, true>,
                         cudaFuncAttributeMaxDynamicSharedMemorySize, GEMM_SMEM);
    cudaFuncSetAttribute((const void*)gemm_wmma_kernel<true, false>,
                         cudaFuncAttributeMaxDynamicSharedMemorySize, GEMM_SMEM);

    prep_kernel<<<2048, 256>>>(W1, W2, erow, E);
    scan1_kernel<<<NCHUNKS, CHUNK>>>();
    // t1 = x @ W1 (fp16 out), real-edge scatter folded in (pads stay zero)
    gemm_wmma_kernel<false, true><<<GEMM_GRID, 512, GEMM_SMEM>>>(
        x, w1h, w1l, ga, N_NODES, nullptr, nullptr, erow, ecol, ew, E);
    // h1 = A @ t1 + b1, fused BN stats
    spmm_csr_kernel<true, false><<<SPMM_GRID, 256>>>(ga, gb, b1);
    // h2 = relu(bn(h1)) @ W2 (fp16 out)
    gemm_wmma_kernel<true, false><<<GEMM_GRID, 512, GEMM_SMEM>>>(
        gb, w2h, w2l, ga, N_PAD, gamma, beta, nullptr, nullptr, nullptr, 0);
    // out = A @ h2 + b2, then reset g_count for next replay
    spmm_csr_kernel<false, true><<<SPMM_GRID, 256>>>(ga, out, b2);
}

// round 17
// speedup vs baseline: 1.0283x; 1.0283x over previous
#include <cuda_runtime.h>
#include <cuda_fp16.h>
#include <cuda_bf16.h>
#include <mma.h>
#include <cstdint>

using namespace nvcuda;

#define N_NODES 100000
#define N_EDGES_MAX 2000000                        // real 1.6M + pad (<=300K)
#define F 128
#define BN_EPS 1e-5f
#define CHUNK 1024
#define NCHUNKS ((N_NODES + CHUNK - 1) / CHUNK)   // 98
#define M_TILE 256
#define N_PAD 100096                               // 391 * 256
#define GEMM_BLOCKS (N_PAD / M_TILE)               // 391
#define GEMM_GRID 148                              // persistent: one CTA per SM
#define GEMM_WAVES ((GEMM_BLOCKS + GEMM_GRID - 1) / GEMM_GRID)  // 3
#define A_STRIDE 136                               // padded smem lda (bf16)
#define B_STRIDE 136
#define SPMM_GRID 888                              // 148 SMs * 6 resident blocks

// Dynamic smem layout for GEMM (bytes)
#define SM_AHI 0
#define SM_ALO (M_TILE * A_STRIDE * 2)             // 69632
#define SM_BHI (2 * M_TILE * A_STRIDE * 2)         // 139264
#define SM_BLO (SM_BHI + F * B_STRIDE * 2)         // +34816
#define GEMM_SMEM (SM_BLO + F * B_STRIDE * 2)      // 208896

// ---------------------------------------------------------------------------
// Scratch (__device__ globals; allocation-free rule).
// g_ecw is zero-initialized at module load. Pad slots are NEVER written and
// the CSR layout is replay-invariant, so pad entries stay {col=0, w=0.0f}
// forever (validated R13/R14).
// ---------------------------------------------------------------------------
__device__ __half g_a[(size_t)N_PAD * F];      // t1 = x@W1, later h2 (fp16)
__device__ float  g_b[(size_t)N_PAD * F];      // h1 (fp32; pad rows stay 0)
__device__ float  g_stats[2 * F];              // [sum, sumsq] per feature
__device__ int    g_count[N_NODES];            // REAL counts; zeroed at launch end
__device__ int    g_row_start[N_NODES + 1];    // chunk-local excl prefix of PADDED counts
__device__ int    g_cursor[N_NODES];
__device__ int    g_chunksum[NCHUNKS];
__device__ int    g_chunkoff[NCHUNKS];
__device__ int    g_ticket;                    // reset by scan1 finisher
__device__ int2   g_ecw[N_EDGES_MAX];          // row-grouped {col, weight-bits}, rows padded to 4
__device__ __nv_bfloat16 g_w1hi[F * F];
__device__ __nv_bfloat16 g_w1lo[F * F];
__device__ __nv_bfloat16 g_w2hi[F * F];
__device__ __nv_bfloat16 g_w2lo[F * F];

// ---------------------------------------------------------------------------
// Prep: zero stats + split W1/W2 into bf16 hi/lo + edge histogram.
// ---------------------------------------------------------------------------
__global__ void prep_kernel(const float* __restrict__ W1, const float* __restrict__ W2,
                            const int* __restrict__ erow, int E) {
    int idx = blockIdx.x * blockDim.x + threadIdx.x;
    int stride = gridDim.x * blockDim.x;
    if (idx < 2 * F) g_stats[idx] = 0.0f;

    for (int i = idx; i < 2 * F * F; i += stride) {
        int m = i >> 14;
        int e = i & (F * F - 1);
        float w = m ? W2[e] : W1[e];
        __nv_bfloat16 hi = __float2bfloat16_rn(w);
        __nv_bfloat16 lo = __float2bfloat16_rn(w - __bfloat162float(hi));
        if (m) { g_w2hi[e] = hi; g_w2lo[e] = lo; }
        else   { g_w1hi[e] = hi; g_w1lo[e] = lo; }
    }

    for (int e = idx; e < E; e += stride)
        atomicAdd(&g_count[erow[e]], 1);
}

// ---------------------------------------------------------------------------
// Per-chunk scan of PADDED counts + last-block finalize (and ticket reset).
// ---------------------------------------------------------------------------
__global__ void scan1_kernel() {
    __shared__ int sm[CHUNK];
    __shared__ int is_last;
    int tid = threadIdx.x;
    int i = blockIdx.x * CHUNK + tid;
    int val = (i < N_NODES) ? ((g_count[i] + 3) & ~3) : 0;   // padded
    sm[tid] = val;
    __syncthreads();
    for (int off = 1; off < CHUNK; off <<= 1) {
        int t = (tid >= off) ? sm[tid - off] : 0;
        __syncthreads();
        sm[tid] += t;
        __syncthreads();
    }
    int excl = sm[tid] - val;
    if (i < N_NODES + 1) g_row_start[i] = excl;
    if (i < N_NODES) g_cursor[i] = excl;
    if (tid == CHUNK - 1) g_chunksum[blockIdx.x] = sm[tid];

    if (tid == 0) {
        __threadfence();
        is_last = (atomicAdd(&g_ticket, 1) == NCHUNKS - 1);
    }
    __syncthreads();
    if (is_last) {
        __shared__ int cs[128];
        if (tid < 128) {
            int v = (tid < NCHUNKS) ? g_chunksum[tid] : 0;
            cs[tid] = v;
            __syncwarp();
        }
        __syncthreads();
        if (tid < 128) {
            for (int off = 1; off < 128; off <<= 1) {
                int t = (tid >= off) ? cs[tid - off] : 0;
                __syncthreads();
                cs[tid] += t;
                __syncthreads();
            }
            if (tid < NCHUNKS) g_chunkoff[tid] = cs[tid] - ((tid < NCHUNKS) ? g_chunksum[tid] : 0);
            if (tid == 0) g_ticket = 0;
        } else {
            for (int off = 1; off < 128; off <<= 1) { __syncthreads(); __syncthreads(); }
        }
    }
}

// ---------------------------------------------------------------------------
// Persistent WMMA bf16 GEMM, 3-term split: outH(fp16) = transform(X fp32) @ W.
// Grid = 148; B copied to smem once; DIRECT fp16 fragment epilogue (proven
// R16: float acc -> half acc elementwise -> store_matrix_sync to global).
// DO_SCATTER pre-phase: scatter real edges (pad slots stay zero from load).
// ---------------------------------------------------------------------------
template <bool FUSE_BN, bool DO_SCATTER>
__global__ void __launch_bounds__(512, 1) gemm_wmma_kernel(
    const float* __restrict__ X,
    const __nv_bfloat16* __restrict__ Whi, const __nv_bfloat16* __restrict__ Wlo,
    __half* __restrict__ outH, int nrows,
    const float* __restrict__ gamma, const float* __restrict__ beta,
    const int* __restrict__ erow, const int* __restrict__ ecol,
    const float* __restrict__ ew, int E) {
    extern __shared__ char smem[];
    __nv_bfloat16* a_hi = (__nv_bfloat16*)(smem + SM_AHI);
    __nv_bfloat16* a_lo = (__nv_bfloat16*)(smem + SM_ALO);
    __nv_bfloat16* b_hi = (__nv_bfloat16*)(smem + SM_BHI);
    __nv_bfloat16* b_lo = (__nv_bfloat16*)(smem + SM_BLO);
    __shared__ float scale_s[F];
    __shared__ float shift_s[F];

    const int tid = threadIdx.x;
    const int wid = tid >> 5;
    const int wm = wid & 7;
    const int wn = wid >> 3;
    const int mrow0 = wm * 32;
    const int ncol0 = wn * 64;

    if (DO_SCATTER) {
        int per = (E + gridDim.x - 1) / (int)gridDim.x;
        int e0 = blockIdx.x * per;
        int e1 = min(e0 + per, E);
        for (int e = e0 + tid; e < e1; e += 512) {
            int r = erow[e];
            int pos = atomicAdd(&g_cursor[r], 1) + g_chunkoff[r >> 10];
            g_ecw[pos] = make_int2(ecol[e], __float_as_int(ew[e]));
        }
    }

    if (FUSE_BN && tid < F) {
        const float inv = 1.0f / (float)N_NODES;
        float mean = g_stats[tid] * inv;
        float var = g_stats[F + tid] * inv - mean * mean;
        float sc = gamma[tid] * rsqrtf(var + BN_EPS);
        scale_s[tid] = sc;
        shift_s[tid] = beta[tid] - mean * sc;
    }

    // Copy B hi/lo into padded smem ONCE (amortized over all tiles)
    {
        const uint2* Bh = (const uint2*)Whi;
        const uint2* Bl = (const uint2*)Wlo;
        for (int i = tid; i < F * 32; i += 512) {
            int r = i >> 5;
            int c = i & 31;
            ((uint2*)&b_hi[r * B_STRIDE])[c] = Bh[i];
            ((uint2*)&b_lo[r * B_STRIDE])[c] = Bl[i];
        }
    }

    const float4* X4 = (const float4*)X;

    for (int wave = 0; wave < GEMM_WAVES; wave++) {
        const int tile = (int)blockIdx.x + wave * GEMM_GRID;
        const bool active = (tile < GEMM_BLOCKS);
        const int row0 = tile * M_TILE;

        // Orders: prev wave's MMA reads of a_hi/a_lo before overwrite;
        // B copy & scale_s before first use.
        __syncthreads();

        if (active) {
            const bool full = (row0 + M_TILE <= nrows);
            for (int i = tid; i < M_TILE * 32; i += 512) {
                int r = i >> 5;
                int c4 = i & 31;
                int gr = row0 + r;
                float4 v = make_float4(0.f, 0.f, 0.f, 0.f);
                if (full || gr < nrows) v = X4[(size_t)gr * 32 + c4];
                if (FUSE_BN) {
                    int f = c4 * 4;
                    v.x = fmaxf(fmaf(v.x, scale_s[f + 0], shift_s[f + 0]), 0.f);
                    v.y = fmaxf(fmaf(v.y, scale_s[f + 1], shift_s[f + 1]), 0.f);
                    v.z = fmaxf(fmaf(v.z, scale_s[f + 2], shift_s[f + 2]), 0.f);
                    v.w = fmaxf(fmaf(v.w, scale_s[f + 3], shift_s[f + 3]), 0.f);
                }
                __nv_bfloat16 hx = __float2bfloat16_rn(v.x), hy = __float2bfloat16_rn(v.y);
                __nv_bfloat16 hz = __float2bfloat16_rn(v.z), hw = __float2bfloat16_rn(v.w);
                __nv_bfloat16 lx = __float2bfloat16_rn(v.x - __bfloat162float(hx));
                __nv_bfloat16 ly = __float2bfloat16_rn(v.y - __bfloat162float(hy));
                __nv_bfloat16 lz = __float2bfloat16_rn(v.z - __bfloat162float(hz));
                __nv_bfloat16 lw = __float2bfloat16_rn(v.w - __bfloat162float(hw));
                int base = r * A_STRIDE + c4 * 4;
                uint2 hp, lp;
                hp.x = (uint32_t)__bfloat16_as_ushort(hx) | ((uint32_t)__bfloat16_as_ushort(hy) << 16);
                hp.y = (uint32_t)__bfloat16_as_ushort(hz) | ((uint32_t)__bfloat16_as_ushort(hw) << 16);
                lp.x = (uint32_t)__bfloat16_as_ushort(lx) | ((uint32_t)__bfloat16_as_ushort(ly) << 16);
                lp.y = (uint32_t)__bfloat16_as_ushort(lz) | ((uint32_t)__bfloat16_as_ushort(lw) << 16);
                *(uint2*)&a_hi[base] = hp;
                *(uint2*)&a_lo[base] = lp;
            }
        }
        __syncthreads();

        if (active) {
            wmma::fragment<wmma::accumulator, 16, 16, 16, float> acc[2][4];
#pragma unroll
            for (int mt = 0; mt < 2; mt++)
#pragma unroll
                for (int nt = 0; nt < 4; nt++)
                    wmma::fill_fragment(acc[mt][nt], 0.0f);

#pragma unroll
            for (int k0 = 0; k0 < F; k0 += 16) {
                wmma::fragment<wmma::matrix_a, 16, 16, 16, __nv_bfloat16, wmma::row_major> ah[2], al[2];
#pragma unroll
                for (int mt = 0; mt < 2; mt++) {
                    wmma::load_matrix_sync(ah[mt], &a_hi[(mrow0 + mt * 16) * A_STRIDE + k0], A_STRIDE);
                    wmma::load_matrix_sync(al[mt], &a_lo[(mrow0 + mt * 16) * A_STRIDE + k0], A_STRIDE);
                }
#pragma unroll
                for (int nt = 0; nt < 4; nt++) {
                    wmma::fragment<wmma::matrix_b, 16, 16, 16, __nv_bfloat16, wmma::row_major> bh, bl;
                    wmma::load_matrix_sync(bh, &b_hi[k0 * B_STRIDE + ncol0 + nt * 16], B_STRIDE);
                    wmma::load_matrix_sync(bl, &b_lo[k0 * B_STRIDE + ncol0 + nt * 16], B_STRIDE);
#pragma unroll
                    for (int mt = 0; mt < 2; mt++) {
                        wmma::mma_sync(acc[mt][nt], ah[mt], bh, acc[mt][nt]);
                        wmma::mma_sync(acc[mt][nt], al[mt], bh, acc[mt][nt]);
                        wmma::mma_sync(acc[mt][nt], ah[mt], bl, acc[mt][nt]);
                    }
                }
            }

            // Direct fp16 epilogue (R16-proven): float acc -> half acc -> global.
#pragma unroll
            for (int mt = 0; mt < 2; mt++) {
                int gr = row0 + mrow0 + mt * 16;
#pragma unroll
                for (int nt = 0; nt < 4; nt++) {
                    wmma::fragment<wmma::accumulator, 16, 16, 16, __half> hacc;
#pragma unroll
                    for (int i = 0; i < hacc.num_elements; i++)
                        hacc.x[i] = __float2half_rn(acc[mt][nt].x[i]);
                    wmma::store_matrix_sync(&outH[(size_t)gr * F + ncol0 + nt * 16],
                                            hacc, F, wmma::mem_row_major);
                }
            }
        }
    }
}

// ---------------------------------------------------------------------------
// CSR SpMM v4 (R12/R14/R15-proven, 52.0us @ grid 888): grid-strided warp per
// row; padded rows -> branch-free 4-wide loop; straight-line uniform int4
// meta LDGs; 4 fp16 gathers in flight; fp32 accumulate.
// ---------------------------------------------------------------------------
template <bool STATS, bool ZERO_COUNT>
__global__ void __launch_bounds__(256, 6) spmm_csr_kernel(
    const __half* __restrict__ src, float* __restrict__ dst,
    const float* __restrict__ bias) {
    const int lane = threadIdx.x & 31;
    const int wid = threadIdx.x >> 5;
    const int gwarp = (blockIdx.x * blockDim.x + threadIdx.x) >> 5;
    const int nwarps = (gridDim.x * blockDim.x) >> 5;

    const uint2* lane_src = (const uint2*)src + lane;   // per-lane base (4 halves)
    float4* dst4 = (float4*)dst;
    const float4 bias4 = ((const float4*)bias)[lane];

    float4 ls = make_float4(0.f, 0.f, 0.f, 0.f);
    float4 lq = make_float4(0.f, 0.f, 0.f, 0.f);

    for (int r = gwarp; r < N_NODES; r += nwarps) {
        const int s = g_row_start[r] + g_chunkoff[r >> 10];
        const int e = g_row_start[r + 1] + g_chunkoff[(r + 1) >> 10];
        float4 acc = bias4;
        for (int j = s; j < e; j += 4) {             // e-s is a multiple of 4
            const int4 ma = *(const int4*)(g_ecw + j);       // edges j, j+1
            const int4 mb = *(const int4*)(g_ecw + j + 2);   // edges j+2, j+3
            uint2 p0 = lane_src[(size_t)ma.x * 32];          // 4 gathers in flight
            uint2 p1 = lane_src[(size_t)ma.z * 32];
            uint2 p2 = lane_src[(size_t)mb.x * 32];
            uint2 p3 = lane_src[(size_t)mb.z * 32];
            float w0 = __int_as_float(ma.y);
            float w1 = __int_as_float(ma.w);
            float w2 = __int_as_float(mb.y);
            float w3 = __int_as_float(mb.w);
            float2 a0 = __half22float2(*(const __half2*)&p0.x);
            float2 b0 = __half22float2(*(const __half2*)&p0.y);
            acc.x = fmaf(a0.x, w0, acc.x); acc.y = fmaf(a0.y, w0, acc.y);
            acc.z = fmaf(b0.x, w0, acc.z); acc.w = fmaf(b0.y, w0, acc.w);
            float2 a1 = __half22float2(*(const __half2*)&p1.x);
            float2 b1 = __half22float2(*(const __half2*)&p1.y);
            acc.x = fmaf(a1.x, w1, acc.x); acc.y = fmaf(a1.y, w1, acc.y);
            acc.z = fmaf(b1.x, w1, acc.z); acc.w = fmaf(b1.y, w1, acc.w);
            float2 a2 = __half22float2(*(const __half2*)&p2.x);
            float2 b2 = __half22float2(*(const __half2*)&p2.y);
            acc.x = fmaf(a2.x, w2, acc.x); acc.y = fmaf(a2.y, w2, acc.y);
            acc.z = fmaf(b2.x, w2, acc.z); acc.w = fmaf(b2.y, w2, acc.w);
            float2 a3 = __half22float2(*(const __half2*)&p3.x);
            float2 b3 = __half22float2(*(const __half2*)&p3.y);
            acc.x = fmaf(a3.x, w3, acc.x); acc.y = fmaf(a3.y, w3, acc.y);
            acc.z = fmaf(b3.x, w3, acc.z); acc.w = fmaf(b3.y, w3, acc.w);
        }
        dst4[(size_t)r * 32 + lane] = acc;
        if (STATS) {
            ls.x += acc.x; ls.y += acc.y; ls.z += acc.z; ls.w += acc.w;
            lq.x = fmaf(acc.x, acc.x, lq.x);
            lq.y = fmaf(acc.y, acc.y, lq.y);
            lq.z = fmaf(acc.z, acc.z, lq.z);
            lq.w = fmaf(acc.w, acc.w, lq.w);
        }
    }

    if (STATS) {
        __shared__ float ssum[8 * F];
        __shared__ float ssq[8 * F];
        *(float4*)&ssum[wid * F + lane * 4] = ls;
        *(float4*)&ssq[wid * F + lane * 4] = lq;
        __syncthreads();
        int tid = threadIdx.x;
        if (tid < F) {
            float s2 = 0.f;
#pragma unroll
            for (int w = 0; w < 8; w++) s2 += ssum[w * F + tid];
            atomicAdd(&g_stats[tid], s2);
        } else {
            int f = tid - F;
            float q = 0.f;
#pragma unroll
            for (int w = 0; w < 8; w++) q += ssq[w * F + f];
            atomicAdd(&g_stats[F + f], q);
        }
    }

    if (ZERO_COUNT) {
        for (int i = blockIdx.x * blockDim.x + threadIdx.x; i < N_NODES;
             i += gridDim.x * blockDim.x)
            g_count[i] = 0;
    }
}

// ---------------------------------------------------------------------------
// Launch
// ---------------------------------------------------------------------------
extern "C" void kernel_launch(void* const* d_in, const int* in_sizes, int n_in,
                              void* d_out, int out_size) {
    const float* x     = (const float*)d_in[0];
    const int*   erow  = (const int*)d_in[1];
    const int*   ecol  = (const int*)d_in[2];
    const float* ew    = (const float*)d_in[3];
    const float* W1    = (const float*)d_in[4];
    const float* b1    = (const float*)d_in[5];
    const float* W2    = (const float*)d_in[6];
    const float* b2    = (const float*)d_in[7];
    const float* gamma = (const float*)d_in[8];
    const float* beta  = (const float*)d_in[9];
    float* out = (float*)d_out;
    const int E = in_sizes[1];

    __half* ga;
    float* gb;
    cudaGetSymbolAddress((void**)&ga, g_a);
    cudaGetSymbolAddress((void**)&gb, g_b);
    __nv_bfloat16 *w1h, *w1l, *w2h, *w2l;
    cudaGetSymbolAddress((void**)&w1h, g_w1hi);
    cudaGetSymbolAddress((void**)&w1l, g_w1lo);
    cudaGetSymbolAddress((void**)&w2h, g_w2hi);
    cudaGetSymbolAddress((void**)&w2l, g_w2lo);

    cudaFuncSetAttribute((const void*)gemm_wmma_kernel<false, true>,
                         cudaFuncAttributeMaxDynamicSharedMemorySize, GEMM_SMEM);
    cudaFuncSetAttribute((const void*)gemm_wmma_kernel<true, false>,
                         cudaFuncAttributeMaxDynamicSharedMemorySize, GEMM_SMEM);

    prep_kernel<<<2048, 256>>>(W1, W2, erow, E);
    scan1_kernel<<<NCHUNKS, CHUNK>>>();
    // t1 = x @ W1 (fp16 out), real-edge scatter folded in (pads stay zero)
    gemm_wmma_kernel<false, true><<<GEMM_GRID, 512, GEMM_SMEM>>>(
        x, w1h, w1l, ga, N_NODES, nullptr, nullptr, erow, ecol, ew, E);
    // h1 = A @ t1 + b1, fused BN stats
    spmm_csr_kernel<true, false><<<SPMM_GRID, 256>>>(ga, gb, b1);
    // h2 = relu(bn(h1)) @ W2 (fp16 out)
    gemm_wmma_kernel<true, false><<<GEMM_GRID, 512, GEMM_SMEM>>>(
        gb, w2h, w2l, ga, N_PAD, gamma, beta, nullptr, nullptr, nullptr, 0);
    // out = A @ h2 + b2, then reset g_count for next replay
    spmm_csr_kernel<false, true><<<SPMM_GRID, 256>>>(ga, out, b2);
}